// round 1
// baseline (speedup 1.0000x reference)
#include <cuda_runtime.h>
#include <cuda_bf16.h>
#include <math.h>

#define BATCH  2
#define TSEQ   2048
#define DMODEL 1024
#define NH     16
#define DKH    64
#define MROWS  (BATCH * TSEQ)   /* 4096 */
#define BHEADS (BATCH * NH)     /* 32 */

// ---------------- scratch (device globals: no allocations allowed) ----------
__device__ float g_Q[(size_t)BHEADS * TSEQ * DKH];   // (B,H,T,DK)
__device__ float g_K[(size_t)BHEADS * TSEQ * DKH];
__device__ float g_V[(size_t)BHEADS * TSEQ * DKH];
__device__ float g_C[(size_t)MROWS * DMODEL];        // combined attn out (B,T,D)
__device__ float g_m[(size_t)BHEADS * TSEQ];         // per-row softmax max
__device__ float g_l[(size_t)BHEADS * TSEQ];         // per-row softmax denom

// ---------------------------------------------------------------------------
// C = A(M x K) @ W(N x K)^T  with M=4096, N=1024, K=1024 (torch Linear)
// 128x128 tile, BK=8, 256 threads, 8x8 per thread (2x2 blocks of 4x4).
// headsplit=1 scatters output into (B,H,T,DK) layout.
// ---------------------------------------------------------------------------
__global__ void __launch_bounds__(256) sgemm_wt(const float* __restrict__ A,
                                               const float* __restrict__ W,
                                               float* __restrict__ Cout,
                                               int headsplit)
{
    const int K = DMODEL;
    __shared__ float As[8][132];
    __shared__ float Bs[8][132];

    const int m0 = blockIdx.y * 128;
    const int n0 = blockIdx.x * 128;
    const int tid = threadIdx.x;
    const int tx = tid & 15;
    const int ty = tid >> 4;
    const int lrow = tid >> 1;        // 0..127
    const int lk   = (tid & 1) << 2;  // 0 or 4

    float acc[2][2][4][4] = {};

    for (int k0 = 0; k0 < K; k0 += 8) {
        float4 av = *(const float4*)(A + (size_t)(m0 + lrow) * K + k0 + lk);
        float4 bv = *(const float4*)(W + (size_t)(n0 + lrow) * K + k0 + lk);
        As[lk + 0][lrow] = av.x; As[lk + 1][lrow] = av.y;
        As[lk + 2][lrow] = av.z; As[lk + 3][lrow] = av.w;
        Bs[lk + 0][lrow] = bv.x; Bs[lk + 1][lrow] = bv.y;
        Bs[lk + 2][lrow] = bv.z; Bs[lk + 3][lrow] = bv.w;
        __syncthreads();

        #pragma unroll
        for (int kk = 0; kk < 8; kk++) {
            float4 a0 = *(const float4*)&As[kk][ty * 4];
            float4 a1 = *(const float4*)&As[kk][64 + ty * 4];
            float4 b0 = *(const float4*)&Bs[kk][tx * 4];
            float4 b1 = *(const float4*)&Bs[kk][64 + tx * 4];
            float a[2][4] = {{a0.x, a0.y, a0.z, a0.w}, {a1.x, a1.y, a1.z, a1.w}};
            float b[2][4] = {{b0.x, b0.y, b0.z, b0.w}, {b1.x, b1.y, b1.z, b1.w}};
            #pragma unroll
            for (int bi = 0; bi < 2; bi++)
                #pragma unroll
                for (int bj = 0; bj < 2; bj++)
                    #pragma unroll
                    for (int i = 0; i < 4; i++)
                        #pragma unroll
                        for (int j = 0; j < 4; j++)
                            acc[bi][bj][i][j] += a[bi][i] * b[bj][j];
        }
        __syncthreads();
    }

    #pragma unroll
    for (int bi = 0; bi < 2; bi++)
        #pragma unroll
        for (int i = 0; i < 4; i++) {
            const int m = m0 + bi * 64 + ty * 4 + i;
            const int bb = m / TSEQ, t = m % TSEQ;
            #pragma unroll
            for (int bj = 0; bj < 2; bj++)
                #pragma unroll
                for (int j = 0; j < 4; j++) {
                    const int n = n0 + bj * 64 + tx * 4 + j;
                    const float v = acc[bi][bj][i][j];
                    if (headsplit) {
                        const int h = n >> 6, dk = n & 63;
                        Cout[(((size_t)bb * NH + h) * TSEQ + t) * DKH + dk] = v;
                    } else {
                        Cout[(size_t)m * DMODEL + n] = v;
                    }
                }
        }
}

// ---------------------------------------------------------------------------
// Flash attention, fp32. Grid (T/64, B*H), 256 threads, 4x4 per thread.
// Q,K stored transposed [d][r] (stride 68) for conflict-free LDS.128.
// Saves row stats (m, l) for the optional attn_weights pass.
// ---------------------------------------------------------------------------
__global__ void __launch_bounds__(256) flash_attn()
{
    extern __shared__ float sm[];
    float* Qst = sm;                 // [64][68] (d-major)
    float* Kst = sm + 64 * 68;       // [64][68] (d-major)
    float* Vs  = sm + 2 * 64 * 68;   // [64][68] (kk-major)
    float* Pst = sm + 3 * 64 * 68;   // [64][68] (kk-major)

    const int bh = blockIdx.y;
    const int b  = bh >> 4;
    const int h  = bh & 15;
    const int q0 = blockIdx.x << 6;

    const float* Qg = g_Q + (size_t)bh * TSEQ * DKH;
    const float* Kg = g_K + (size_t)bh * TSEQ * DKH;
    const float* Vg = g_V + (size_t)bh * TSEQ * DKH;

    const int tid = threadIdx.x;
    const int tx = tid & 15;
    const int ty = tid >> 4;

    // load Q tile transposed
    for (int i = tid; i < 64 * 16; i += 256) {
        const int r = i >> 4, c4 = (i & 15) << 2;
        float4 v = *(const float4*)(Qg + (size_t)(q0 + r) * DKH + c4);
        Qst[(c4 + 0) * 68 + r] = v.x;
        Qst[(c4 + 1) * 68 + r] = v.y;
        Qst[(c4 + 2) * 68 + r] = v.z;
        Qst[(c4 + 3) * 68 + r] = v.w;
    }

    float m_i[4], l_i[4], O[4][4];
    #pragma unroll
    for (int i = 0; i < 4; i++) {
        m_i[i] = -INFINITY; l_i[i] = 0.f;
        #pragma unroll
        for (int j = 0; j < 4; j++) O[i][j] = 0.f;
    }

    for (int k0 = 0; k0 <= q0; k0 += 64) {
        __syncthreads();  // previous iteration done with Kst/Vs/Pst
        for (int i = tid; i < 64 * 16; i += 256) {
            const int r = i >> 4, c4 = (i & 15) << 2;
            float4 kv = *(const float4*)(Kg + (size_t)(k0 + r) * DKH + c4);
            Kst[(c4 + 0) * 68 + r] = kv.x;
            Kst[(c4 + 1) * 68 + r] = kv.y;
            Kst[(c4 + 2) * 68 + r] = kv.z;
            Kst[(c4 + 3) * 68 + r] = kv.w;
            float4 vv = *(const float4*)(Vg + (size_t)(k0 + r) * DKH + c4);
            float* vrow = Vs + r * 68 + c4;
            vrow[0] = vv.x; vrow[1] = vv.y; vrow[2] = vv.z; vrow[3] = vv.w;
        }
        __syncthreads();

        // S = Q @ K^T
        float S[4][4] = {};
        #pragma unroll 8
        for (int d = 0; d < 64; d++) {
            float4 qa = *(const float4*)&Qst[d * 68 + ty * 4];
            float4 kb = *(const float4*)&Kst[d * 68 + tx * 4];
            float qv[4] = {qa.x, qa.y, qa.z, qa.w};
            float kv[4] = {kb.x, kb.y, kb.z, kb.w};
            #pragma unroll
            for (int i = 0; i < 4; i++)
                #pragma unroll
                for (int j = 0; j < 4; j++)
                    S[i][j] += qv[i] * kv[j];
        }

        const bool diag = (k0 == q0);
        #pragma unroll
        for (int i = 0; i < 4; i++)
            #pragma unroll
            for (int j = 0; j < 4; j++) {
                S[i][j] *= 0.125f;  // 1/sqrt(64)
                if (diag && (k0 + tx * 4 + j > q0 + ty * 4 + i)) S[i][j] = -1e30f;
            }

        // online softmax
        #pragma unroll
        for (int i = 0; i < 4; i++) {
            float rm = fmaxf(fmaxf(S[i][0], S[i][1]), fmaxf(S[i][2], S[i][3]));
            #pragma unroll
            for (int off = 8; off; off >>= 1)
                rm = fmaxf(rm, __shfl_xor_sync(0xffffffffu, rm, off, 16));
            const float m_new = fmaxf(m_i[i], rm);
            const float alpha = expf(m_i[i] - m_new);
            float rs = 0.f;
            #pragma unroll
            for (int j = 0; j < 4; j++) {
                S[i][j] = expf(S[i][j] - m_new);
                rs += S[i][j];
            }
            #pragma unroll
            for (int off = 8; off; off >>= 1)
                rs += __shfl_xor_sync(0xffffffffu, rs, off, 16);
            l_i[i] = l_i[i] * alpha + rs;
            m_i[i] = m_new;
            #pragma unroll
            for (int j = 0; j < 4; j++) O[i][j] *= alpha;
        }

        // store P transposed [kk][r]
        #pragma unroll
        for (int i = 0; i < 4; i++)
            #pragma unroll
            for (int j = 0; j < 4; j++)
                Pst[(tx * 4 + j) * 68 + (ty * 4 + i)] = S[i][j];
        __syncthreads();

        // O += P @ V
        #pragma unroll 8
        for (int kk = 0; kk < 64; kk++) {
            float4 pa = *(const float4*)&Pst[kk * 68 + ty * 4];
            float4 vb = *(const float4*)&Vs[kk * 68 + tx * 4];
            float pv[4] = {pa.x, pa.y, pa.z, pa.w};
            float vv[4] = {vb.x, vb.y, vb.z, vb.w};
            #pragma unroll
            for (int i = 0; i < 4; i++)
                #pragma unroll
                for (int j = 0; j < 4; j++)
                    O[i][j] += pv[i] * vv[j];
        }
    }

    // finalize: write combined (B,T,D) layout and save row stats
    #pragma unroll
    for (int i = 0; i < 4; i++) {
        const int q = q0 + ty * 4 + i;
        const float inv_l = 1.f / l_i[i];
        float4 o4;
        o4.x = O[i][0] * inv_l; o4.y = O[i][1] * inv_l;
        o4.z = O[i][2] * inv_l; o4.w = O[i][3] * inv_l;
        *(float4*)(g_C + (size_t)(b * TSEQ + q) * DMODEL + h * DKH + tx * 4) = o4;
        if (tx == 0) {
            g_m[(size_t)bh * TSEQ + q] = m_i[i];
            g_l[(size_t)bh * TSEQ + q] = l_i[i];
        }
    }
}

// ---------------------------------------------------------------------------
// attn_weights pass: recompute score tiles, emit exp(s-m)/l; zero masked area.
// Grid (T/64 kt, T/64 qt, B*H), 256 threads, 4x4 per thread.
// ---------------------------------------------------------------------------
__global__ void __launch_bounds__(256) attn_weights(float* __restrict__ AW)
{
    const int bh = blockIdx.z;
    const int q0 = blockIdx.y << 6;
    const int k0 = blockIdx.x << 6;
    const int tid = threadIdx.x;
    const int tx = tid & 15;
    const int ty = tid >> 4;
    const size_t base = (size_t)bh * TSEQ * TSEQ;

    if (k0 > q0 + 63) {  // fully masked tile: must still write (d_out poisoned)
        const float4 z = {0.f, 0.f, 0.f, 0.f};
        #pragma unroll
        for (int i = 0; i < 4; i++)
            *(float4*)(AW + base + (size_t)(q0 + ty * 4 + i) * TSEQ + k0 + tx * 4) = z;
        return;
    }

    __shared__ float Qst[64 * 68];
    __shared__ float Kst[64 * 68];
    const float* Qg = g_Q + (size_t)bh * TSEQ * DKH;
    const float* Kg = g_K + (size_t)bh * TSEQ * DKH;

    for (int i = tid; i < 64 * 16; i += 256) {
        const int r = i >> 4, c4 = (i & 15) << 2;
        float4 qv = *(const float4*)(Qg + (size_t)(q0 + r) * DKH + c4);
        Qst[(c4 + 0) * 68 + r] = qv.x;
        Qst[(c4 + 1) * 68 + r] = qv.y;
        Qst[(c4 + 2) * 68 + r] = qv.z;
        Qst[(c4 + 3) * 68 + r] = qv.w;
        float4 kv = *(const float4*)(Kg + (size_t)(k0 + r) * DKH + c4);
        Kst[(c4 + 0) * 68 + r] = kv.x;
        Kst[(c4 + 1) * 68 + r] = kv.y;
        Kst[(c4 + 2) * 68 + r] = kv.z;
        Kst[(c4 + 3) * 68 + r] = kv.w;
    }
    __syncthreads();

    float S[4][4] = {};
    #pragma unroll 8
    for (int d = 0; d < 64; d++) {
        float4 qa = *(const float4*)&Qst[d * 68 + ty * 4];
        float4 kb = *(const float4*)&Kst[d * 68 + tx * 4];
        float qv[4] = {qa.x, qa.y, qa.z, qa.w};
        float kv[4] = {kb.x, kb.y, kb.z, kb.w};
        #pragma unroll
        for (int i = 0; i < 4; i++)
            #pragma unroll
            for (int j = 0; j < 4; j++)
                S[i][j] += qv[i] * kv[j];
    }

    #pragma unroll
    for (int i = 0; i < 4; i++) {
        const int q = q0 + ty * 4 + i;
        const float mm = g_m[(size_t)bh * TSEQ + q];
        const float il = 1.f / g_l[(size_t)bh * TSEQ + q];
        float4 w4;
        float w[4];
        #pragma unroll
        for (int j = 0; j < 4; j++) {
            const int k = k0 + tx * 4 + j;
            w[j] = (k <= q) ? expf(S[i][j] * 0.125f - mm) * il : 0.f;
        }
        w4.x = w[0]; w4.y = w[1]; w4.z = w[2]; w4.w = w[3];
        *(float4*)(AW + base + (size_t)q * TSEQ + k0 + tx * 4) = w4;
    }
}

// ---------------------------------------------------------------------------
extern "C" void kernel_launch(void* const* d_in, const int* in_sizes, int n_in,
                              void* d_out, int out_size)
{
    const float* q  = (const float*)d_in[0];
    const float* k  = (const float*)d_in[1];
    const float* v  = (const float*)d_in[2];
    // d_in[3] = mask (causal by construction; applied analytically)
    const float* Wq = (const float*)d_in[4];
    const float* Wk = (const float*)d_in[5];
    const float* Wv = (const float*)d_in[6];
    const float* Wo = (const float*)d_in[7];
    float* out = (float*)d_out;

    void *pQ, *pK, *pV, *pC;
    cudaGetSymbolAddress(&pQ, g_Q);
    cudaGetSymbolAddress(&pK, g_K);
    cudaGetSymbolAddress(&pV, g_V);
    cudaGetSymbolAddress(&pC, g_C);

    const dim3 gg(DMODEL / 128, MROWS / 128);  // (8, 32)
    sgemm_wt<<<gg, 256>>>(q, Wq, (float*)pQ, 1);
    sgemm_wt<<<gg, 256>>>(k, Wk, (float*)pK, 1);
    sgemm_wt<<<gg, 256>>>(v, Wv, (float*)pV, 1);

    const int smem = 4 * 64 * 68 * (int)sizeof(float);  // 69632 B
    cudaFuncSetAttribute(flash_attn, cudaFuncAttributeMaxDynamicSharedMemorySize, smem);
    flash_attn<<<dim3(TSEQ / 64, BHEADS), 256, smem>>>();

    sgemm_wt<<<gg, 256>>>((const float*)pC, Wo, out, 0);

    const long long n_out = (long long)MROWS * DMODEL;                 // 4,194,304
    const long long n_aw  = (long long)BHEADS * TSEQ * TSEQ;           // 134,217,728
    if ((long long)out_size >= n_out + n_aw) {
        attn_weights<<<dim3(TSEQ / 64, TSEQ / 64, BHEADS), 256>>>(out + (size_t)n_out);
    }
}

// round 3
// speedup vs baseline: 1.3620x; 1.3620x over previous
#include <cuda_runtime.h>
#include <cuda_bf16.h>
#include <math.h>
#include <stdint.h>

#define BATCH  2
#define TSEQ   2048
#define DMODEL 1024
#define NH     16
#define DKH    64
#define MROWS  (BATCH * TSEQ)   /* 4096 */
#define BHEADS (BATCH * NH)     /* 32 */
#define K3     3072             /* extended K for bf16-split GEMM */

// ---------------- scratch (device globals: no allocations allowed) ----------
__device__ float g_Q[(size_t)BHEADS * TSEQ * DKH];   // (B,H,T,DK)
__device__ float g_K[(size_t)BHEADS * TSEQ * DKH];
__device__ float g_V[(size_t)BHEADS * TSEQ * DKH];
__device__ float g_C[(size_t)MROWS * DMODEL];        // combined attn out (B,T,D)
__device__ float g_m[(size_t)BHEADS * TSEQ];         // per-row softmax max
__device__ float g_l[(size_t)BHEADS * TSEQ];         // per-row softmax denom
__device__ __nv_bfloat16 g_A3[(size_t)MROWS * K3];   // [hi|hi|lo] activations
__device__ __nv_bfloat16 g_W3[(size_t)DMODEL * K3];  // [hi|lo|hi] weights

// ---------------------------------------------------------------------------
// PTX helpers (sm_80-era ISA only: cp.async, ldmatrix, mma.sync)
// ---------------------------------------------------------------------------
__device__ __forceinline__ uint32_t smem_u32(const void* p) {
    uint32_t a;
    asm("{ .reg .u64 t; cvta.to.shared.u64 t, %1; cvt.u32.u64 %0, t; }"
        : "=r"(a) : "l"(p));
    return a;
}
__device__ __forceinline__ void cp16(uint32_t dst, const void* src) {
    asm volatile("cp.async.cg.shared.global [%0], [%1], 16;" :: "r"(dst), "l"(src));
}
__device__ __forceinline__ void cp_commit() {
    asm volatile("cp.async.commit_group;" ::: "memory");
}
template<int N> __device__ __forceinline__ void cp_wait() {
    asm volatile("cp.async.wait_group %0;" :: "n"(N) : "memory");
}
__device__ __forceinline__ void ldsm_x4(uint32_t* r, uint32_t addr) {
    asm volatile("ldmatrix.sync.aligned.m8n8.x4.shared.b16 {%0,%1,%2,%3}, [%4];"
        : "=r"(r[0]), "=r"(r[1]), "=r"(r[2]), "=r"(r[3]) : "r"(addr));
}
__device__ __forceinline__ void mma16816(float* c, const uint32_t* a,
                                         uint32_t b0, uint32_t b1) {
    asm volatile("mma.sync.aligned.m16n8k16.row.col.f32.bf16.bf16.f32 "
        "{%0,%1,%2,%3}, {%4,%5,%6,%7}, {%8,%9}, {%0,%1,%2,%3};"
        : "+f"(c[0]), "+f"(c[1]), "+f"(c[2]), "+f"(c[3])
        : "r"(a[0]), "r"(a[1]), "r"(a[2]), "r"(a[3]), "r"(b0), "r"(b1));
}

// ---------------------------------------------------------------------------
// fp32 -> bf16-split conversion.
// act=1: layout [hi | hi | lo]; act=0 (weights): [hi | lo | hi]
// ---------------------------------------------------------------------------
__global__ void __launch_bounds__(256) convert_split(const float* __restrict__ X,
                                                     __nv_bfloat16* __restrict__ X3,
                                                     int rows, int act)
{
    size_t idx = (size_t)blockIdx.x * blockDim.x + threadIdx.x;  // float4 index
    size_t total = (size_t)rows * DMODEL / 4;
    if (idx >= total) return;
    const int m  = (int)(idx / (DMODEL / 4));
    const int k4 = (int)(idx % (DMODEL / 4)) * 4;
    float4 v = *(const float4*)(X + (size_t)m * DMODEL + k4);
    float f[4] = {v.x, v.y, v.z, v.w};
    __nv_bfloat16 hi[4], lo[4];
    #pragma unroll
    for (int j = 0; j < 4; j++) {
        hi[j] = __float2bfloat16_rn(f[j]);
        lo[j] = __float2bfloat16_rn(f[j] - __bfloat162float(hi[j]));
    }
    __nv_bfloat16* row = X3 + (size_t)m * K3;
    *(uint2*)(row + k4) = *(uint2*)hi;
    if (act) {
        *(uint2*)(row + 1024 + k4) = *(uint2*)hi;
        *(uint2*)(row + 2048 + k4) = *(uint2*)lo;
    } else {
        *(uint2*)(row + 1024 + k4) = *(uint2*)lo;
        *(uint2*)(row + 2048 + k4) = *(uint2*)hi;
    }
}

// ---------------------------------------------------------------------------
// HMMA GEMM: C(M x N) = A3(M x K3) @ B3(N x K3)^T, fp32 out.
// CTA 128x128, BK=32, 256 threads (8 warps, 2x4), warp tile 64x32.
// Padded smem stride 40 bf16 (80B) -> conflict-free ldmatrix.
// ---------------------------------------------------------------------------
#define BK   32
#define SSTR 40
#define NIT  (K3 / BK)   /* 96 */

__global__ void __launch_bounds__(256) gemm_mma(const __nv_bfloat16* __restrict__ A3,
                                                const __nv_bfloat16* __restrict__ B3,
                                                float* __restrict__ Cout,
                                                int headsplit)
{
    __shared__ __nv_bfloat16 sA[2][128 * SSTR];
    __shared__ __nv_bfloat16 sB[2][128 * SSTR];

    const int tid  = threadIdx.x;
    const int wid  = tid >> 5;
    const int lane = tid & 31;
    const int m0 = blockIdx.y * 128;
    const int n0 = blockIdx.x * 128;
    const int wm0 = (wid & 1) * 64;   // warp M offset
    const int wn0 = (wid >> 1) * 32;  // warp N offset

    const uint32_t sAu = smem_u32(sA);
    const uint32_t sBu = smem_u32(sB);
    const uint32_t stage_bytes = 128 * SSTR * 2;

    // loader mapping: each thread: one row, two 16B chunks
    const int lrow = tid >> 1;
    const int lc0  = (tid & 1) * 2;
    const __nv_bfloat16* agp = A3 + (size_t)(m0 + lrow) * K3 + lc0 * 8;
    const __nv_bfloat16* bgp = B3 + (size_t)(n0 + lrow) * K3 + lc0 * 8;
    const uint32_t sAoff = sAu + ((uint32_t)lrow * SSTR + lc0 * 8) * 2;
    const uint32_t sBoff = sBu + ((uint32_t)lrow * SSTR + lc0 * 8) * 2;

    #define LOAD_STAGE(it, s) do {                                   \
        const int kc = (it) * BK;                                    \
        uint32_t so = (uint32_t)(s) * stage_bytes;                   \
        cp16(sAoff + so,      agp + kc);                             \
        cp16(sAoff + so + 16, agp + kc + 8);                         \
        cp16(sBoff + so,      bgp + kc);                             \
        cp16(sBoff + so + 16, bgp + kc + 8);                         \
        cp_commit();                                                 \
    } while (0)

    float acc[4][4][4];
    #pragma unroll
    for (int a = 0; a < 4; a++)
        #pragma unroll
        for (int b = 0; b < 4; b++)
            #pragma unroll
            for (int c = 0; c < 4; c++) acc[a][b][c] = 0.f;

    // ldmatrix lane addressing (same pattern for A and B):
    // row = base + (lane & 15), k element offset = kstep*16 + (lane>>4)*8
    const uint32_t lrsel = lane & 15;
    const uint32_t lkoff = (lane >> 4) * 8;

    LOAD_STAGE(0, 0);

    for (int it = 0; it < NIT; it++) {
        const int s = it & 1;
        if (it + 1 < NIT) { LOAD_STAGE(it + 1, (it + 1) & 1); cp_wait<1>(); }
        else              { cp_wait<0>(); }
        __syncthreads();

        const uint32_t aBase = sAu + s * stage_bytes;
        const uint32_t bBase = sBu + s * stage_bytes;

        #pragma unroll
        for (int ks = 0; ks < 2; ks++) {
            const uint32_t koff = ks * 16 + lkoff;
            uint32_t af[4][4], bf[2][4];
            #pragma unroll
            for (int mt = 0; mt < 4; mt++)
                ldsm_x4(af[mt], aBase + (((uint32_t)(wm0 + mt * 16) + lrsel) * SSTR + koff) * 2);
            #pragma unroll
            for (int bp = 0; bp < 2; bp++)
                ldsm_x4(bf[bp], bBase + (((uint32_t)(wn0 + bp * 16) + lrsel) * SSTR + koff) * 2);
            #pragma unroll
            for (int mt = 0; mt < 4; mt++)
                #pragma unroll
                for (int ng = 0; ng < 4; ng++) {
                    const int bp = ng >> 1, lo = ng & 1;
                    mma16816(acc[mt][ng], af[mt], bf[bp][lo], bf[bp][lo + 2]);
                }
        }
        __syncthreads();
    }

    // epilogue: c0,c1 = (row, col..col+1); c2,c3 = (row+8, col..col+1)
    const int crow = lane >> 2;
    const int ccol = (lane & 3) * 2;
    #pragma unroll
    for (int mt = 0; mt < 4; mt++) {
        #pragma unroll
        for (int half = 0; half < 2; half++) {
            const int m = m0 + wm0 + mt * 16 + crow + half * 8;
            const int bb = m / TSEQ, t = m % TSEQ;
            #pragma unroll
            for (int ng = 0; ng < 4; ng++) {
                const int n = n0 + wn0 + ng * 8 + ccol;
                float2 o;
                o.x = acc[mt][ng][half * 2 + 0];
                o.y = acc[mt][ng][half * 2 + 1];
                if (headsplit) {
                    const int h = n >> 6, dk = n & 63;
                    *(float2*)(Cout + (((size_t)bb * NH + h) * TSEQ + t) * DKH + dk) = o;
                } else {
                    *(float2*)(Cout + (size_t)m * DMODEL + n) = o;
                }
            }
        }
    }
}

// ---------------------------------------------------------------------------
// Flash attention, fp32 (unchanged). Grid (T/64, B*H), 256 threads.
// ---------------------------------------------------------------------------
__global__ void __launch_bounds__(256) flash_attn()
{
    extern __shared__ float sm[];
    float* Qst = sm;
    float* Kst = sm + 64 * 68;
    float* Vs  = sm + 2 * 64 * 68;
    float* Pst = sm + 3 * 64 * 68;

    const int bh = blockIdx.y;
    const int b  = bh >> 4;
    const int h  = bh & 15;
    const int q0 = blockIdx.x << 6;

    const float* Qg = g_Q + (size_t)bh * TSEQ * DKH;
    const float* Kg = g_K + (size_t)bh * TSEQ * DKH;
    const float* Vg = g_V + (size_t)bh * TSEQ * DKH;

    const int tid = threadIdx.x;
    const int tx = tid & 15;
    const int ty = tid >> 4;

    for (int i = tid; i < 64 * 16; i += 256) {
        const int r = i >> 4, c4 = (i & 15) << 2;
        float4 v = *(const float4*)(Qg + (size_t)(q0 + r) * DKH + c4);
        Qst[(c4 + 0) * 68 + r] = v.x;
        Qst[(c4 + 1) * 68 + r] = v.y;
        Qst[(c4 + 2) * 68 + r] = v.z;
        Qst[(c4 + 3) * 68 + r] = v.w;
    }

    float m_i[4], l_i[4], O[4][4];
    #pragma unroll
    for (int i = 0; i < 4; i++) {
        m_i[i] = -INFINITY; l_i[i] = 0.f;
        #pragma unroll
        for (int j = 0; j < 4; j++) O[i][j] = 0.f;
    }

    for (int k0 = 0; k0 <= q0; k0 += 64) {
        __syncthreads();
        for (int i = tid; i < 64 * 16; i += 256) {
            const int r = i >> 4, c4 = (i & 15) << 2;
            float4 kv = *(const float4*)(Kg + (size_t)(k0 + r) * DKH + c4);
            Kst[(c4 + 0) * 68 + r] = kv.x;
            Kst[(c4 + 1) * 68 + r] = kv.y;
            Kst[(c4 + 2) * 68 + r] = kv.z;
            Kst[(c4 + 3) * 68 + r] = kv.w;
            float4 vv = *(const float4*)(Vg + (size_t)(k0 + r) * DKH + c4);
            float* vrow = Vs + r * 68 + c4;
            vrow[0] = vv.x; vrow[1] = vv.y; vrow[2] = vv.z; vrow[3] = vv.w;
        }
        __syncthreads();

        float S[4][4] = {};
        #pragma unroll 8
        for (int d = 0; d < 64; d++) {
            float4 qa = *(const float4*)&Qst[d * 68 + ty * 4];
            float4 kb = *(const float4*)&Kst[d * 68 + tx * 4];
            float qv[4] = {qa.x, qa.y, qa.z, qa.w};
            float kv[4] = {kb.x, kb.y, kb.z, kb.w};
            #pragma unroll
            for (int i = 0; i < 4; i++)
                #pragma unroll
                for (int j = 0; j < 4; j++)
                    S[i][j] += qv[i] * kv[j];
        }

        const bool diag = (k0 == q0);
        #pragma unroll
        for (int i = 0; i < 4; i++)
            #pragma unroll
            for (int j = 0; j < 4; j++) {
                S[i][j] *= 0.125f;
                if (diag && (k0 + tx * 4 + j > q0 + ty * 4 + i)) S[i][j] = -1e30f;
            }

        #pragma unroll
        for (int i = 0; i < 4; i++) {
            float rm = fmaxf(fmaxf(S[i][0], S[i][1]), fmaxf(S[i][2], S[i][3]));
            #pragma unroll
            for (int off = 8; off; off >>= 1)
                rm = fmaxf(rm, __shfl_xor_sync(0xffffffffu, rm, off, 16));
            const float m_new = fmaxf(m_i[i], rm);
            const float alpha = expf(m_i[i] - m_new);
            float rs = 0.f;
            #pragma unroll
            for (int j = 0; j < 4; j++) {
                S[i][j] = expf(S[i][j] - m_new);
                rs += S[i][j];
            }
            #pragma unroll
            for (int off = 8; off; off >>= 1)
                rs += __shfl_xor_sync(0xffffffffu, rs, off, 16);
            l_i[i] = l_i[i] * alpha + rs;
            m_i[i] = m_new;
            #pragma unroll
            for (int j = 0; j < 4; j++) O[i][j] *= alpha;
        }

        #pragma unroll
        for (int i = 0; i < 4; i++)
            #pragma unroll
            for (int j = 0; j < 4; j++)
                Pst[(tx * 4 + j) * 68 + (ty * 4 + i)] = S[i][j];
        __syncthreads();

        #pragma unroll 8
        for (int kk = 0; kk < 64; kk++) {
            float4 pa = *(const float4*)&Pst[kk * 68 + ty * 4];
            float4 vb = *(const float4*)&Vs[kk * 68 + tx * 4];
            float pv[4] = {pa.x, pa.y, pa.z, pa.w};
            float vv[4] = {vb.x, vb.y, vb.z, vb.w};
            #pragma unroll
            for (int i = 0; i < 4; i++)
                #pragma unroll
                for (int j = 0; j < 4; j++)
                    O[i][j] += pv[i] * vv[j];
        }
    }

    #pragma unroll
    for (int i = 0; i < 4; i++) {
        const int q = q0 + ty * 4 + i;
        const float inv_l = 1.f / l_i[i];
        float4 o4;
        o4.x = O[i][0] * inv_l; o4.y = O[i][1] * inv_l;
        o4.z = O[i][2] * inv_l; o4.w = O[i][3] * inv_l;
        *(float4*)(g_C + (size_t)(b * TSEQ + q) * DMODEL + h * DKH + tx * 4) = o4;
        if (tx == 0) {
            g_m[(size_t)bh * TSEQ + q] = m_i[i];
            g_l[(size_t)bh * TSEQ + q] = l_i[i];
        }
    }
}

// ---------------------------------------------------------------------------
// attn_weights pass (optional, unchanged)
// ---------------------------------------------------------------------------
__global__ void __launch_bounds__(256) attn_weights(float* __restrict__ AW)
{
    const int bh = blockIdx.z;
    const int q0 = blockIdx.y << 6;
    const int k0 = blockIdx.x << 6;
    const int tid = threadIdx.x;
    const int tx = tid & 15;
    const int ty = tid >> 4;
    const size_t base = (size_t)bh * TSEQ * TSEQ;

    if (k0 > q0 + 63) {
        const float4 z = {0.f, 0.f, 0.f, 0.f};
        #pragma unroll
        for (int i = 0; i < 4; i++)
            *(float4*)(AW + base + (size_t)(q0 + ty * 4 + i) * TSEQ + k0 + tx * 4) = z;
        return;
    }

    __shared__ float Qst[64 * 68];
    __shared__ float Kst[64 * 68];
    const float* Qg = g_Q + (size_t)bh * TSEQ * DKH;
    const float* Kg = g_K + (size_t)bh * TSEQ * DKH;

    for (int i = tid; i < 64 * 16; i += 256) {
        const int r = i >> 4, c4 = (i & 15) << 2;
        float4 qv = *(const float4*)(Qg + (size_t)(q0 + r) * DKH + c4);
        Qst[(c4 + 0) * 68 + r] = qv.x;
        Qst[(c4 + 1) * 68 + r] = qv.y;
        Qst[(c4 + 2) * 68 + r] = qv.z;
        Qst[(c4 + 3) * 68 + r] = qv.w;
        float4 kv = *(const float4*)(Kg + (size_t)(k0 + r) * DKH + c4);
        Kst[(c4 + 0) * 68 + r] = kv.x;
        Kst[(c4 + 1) * 68 + r] = kv.y;
        Kst[(c4 + 2) * 68 + r] = kv.z;
        Kst[(c4 + 3) * 68 + r] = kv.w;
    }
    __syncthreads();

    float S[4][4] = {};
    #pragma unroll 8
    for (int d = 0; d < 64; d++) {
        float4 qa = *(const float4*)&Qst[d * 68 + ty * 4];
        float4 kb = *(const float4*)&Kst[d * 68 + tx * 4];
        float qv[4] = {qa.x, qa.y, qa.z, qa.w};
        float kv[4] = {kb.x, kb.y, kb.z, kb.w};
        #pragma unroll
        for (int i = 0; i < 4; i++)
            #pragma unroll
            for (int j = 0; j < 4; j++)
                S[i][j] += qv[i] * kv[j];
    }

    #pragma unroll
    for (int i = 0; i < 4; i++) {
        const int q = q0 + ty * 4 + i;
        const float mm = g_m[(size_t)bh * TSEQ + q];
        const float il = 1.f / g_l[(size_t)bh * TSEQ + q];
        float4 w4;
        float w[4];
        #pragma unroll
        for (int j = 0; j < 4; j++) {
            const int k = k0 + tx * 4 + j;
            w[j] = (k <= q) ? expf(S[i][j] * 0.125f - mm) * il : 0.f;
        }
        w4.x = w[0]; w4.y = w[1]; w4.z = w[2]; w4.w = w[3];
        *(float4*)(AW + base + (size_t)q * TSEQ + k0 + tx * 4) = w4;
    }
}

// ---------------------------------------------------------------------------
extern "C" void kernel_launch(void* const* d_in, const int* in_sizes, int n_in,
                              void* d_out, int out_size)
{
    const float* q  = (const float*)d_in[0];
    const float* k  = (const float*)d_in[1];
    const float* v  = (const float*)d_in[2];
    // d_in[3] = mask (causal by construction; applied analytically)
    const float* Wq = (const float*)d_in[4];
    const float* Wk = (const float*)d_in[5];
    const float* Wv = (const float*)d_in[6];
    const float* Wo = (const float*)d_in[7];
    float* out = (float*)d_out;

    void *pQ, *pK, *pV, *pC, *pA3, *pW3;
    cudaGetSymbolAddress(&pQ, g_Q);
    cudaGetSymbolAddress(&pK, g_K);
    cudaGetSymbolAddress(&pV, g_V);
    cudaGetSymbolAddress(&pC, g_C);
    cudaGetSymbolAddress(&pA3, g_A3);
    cudaGetSymbolAddress(&pW3, g_W3);
    __nv_bfloat16* A3 = (__nv_bfloat16*)pA3;
    __nv_bfloat16* W3 = (__nv_bfloat16*)pW3;

    const int cva = (MROWS * DMODEL / 4 + 255) / 256;   // activation conversion grid
    const int cvw = (DMODEL * DMODEL / 4 + 255) / 256;  // weight conversion grid
    const dim3 gg(DMODEL / 128, MROWS / 128);           // (8, 32)

    convert_split<<<cva, 256>>>(q, A3, MROWS, 1);
    convert_split<<<cvw, 256>>>(Wq, W3, DMODEL, 0);
    gemm_mma<<<gg, 256>>>(A3, W3, (float*)pQ, 1);

    convert_split<<<cva, 256>>>(k, A3, MROWS, 1);
    convert_split<<<cvw, 256>>>(Wk, W3, DMODEL, 0);
    gemm_mma<<<gg, 256>>>(A3, W3, (float*)pK, 1);

    convert_split<<<cva, 256>>>(v, A3, MROWS, 1);
    convert_split<<<cvw, 256>>>(Wv, W3, DMODEL, 0);
    gemm_mma<<<gg, 256>>>(A3, W3, (float*)pV, 1);

    const int smem = 4 * 64 * 68 * (int)sizeof(float);  // 69632 B
    cudaFuncSetAttribute(flash_attn, cudaFuncAttributeMaxDynamicSharedMemorySize, smem);
    flash_attn<<<dim3(TSEQ / 64, BHEADS), 256, smem>>>();

    convert_split<<<cva, 256>>>((const float*)pC, A3, MROWS, 1);
    convert_split<<<cvw, 256>>>(Wo, W3, DMODEL, 0);
    gemm_mma<<<gg, 256>>>(A3, W3, out, 0);

    const long long n_out = (long long)MROWS * DMODEL;
    const long long n_aw  = (long long)BHEADS * TSEQ * TSEQ;
    if ((long long)out_size >= n_out + n_aw) {
        attn_weights<<<dim3(TSEQ / 64, TSEQ / 64, BHEADS), 256>>>(out + (size_t)n_out);
    }
}

// round 4
// speedup vs baseline: 1.9182x; 1.4084x over previous
#include <cuda_runtime.h>
#include <cuda_bf16.h>
#include <math.h>
#include <stdint.h>

#define BATCH  2
#define TSEQ   2048
#define DMODEL 1024
#define NH     16
#define DKH    64
#define MROWS  (BATCH * TSEQ)   /* 4096 */
#define BHEADS (BATCH * NH)     /* 32 */
#define K3     3072             /* extended K for bf16-split GEMM */

// ---------------- scratch (device globals: no allocations allowed) ----------
__device__ float g_Q[(size_t)BHEADS * TSEQ * DKH];   // (B,H,T,DK) fp32
__device__ float g_K[(size_t)BHEADS * TSEQ * DKH];
__device__ float g_V[(size_t)BHEADS * TSEQ * DKH];
__device__ float g_C[(size_t)MROWS * DMODEL];        // combined attn out (B,T,D)
__device__ float g_m[(size_t)BHEADS * TSEQ];         // per-row softmax max
__device__ float g_l[(size_t)BHEADS * TSEQ];         // per-row softmax denom
__device__ __nv_bfloat16 g_A3[(size_t)MROWS * K3];   // [hi|hi|lo] activations
__device__ __nv_bfloat16 g_W3[(size_t)DMODEL * K3];  // [hi|lo|hi] weights
__device__ __nv_bfloat16 g_Qh[(size_t)BHEADS * TSEQ * DKH];
__device__ __nv_bfloat16 g_Ql[(size_t)BHEADS * TSEQ * DKH];
__device__ __nv_bfloat16 g_Kh[(size_t)BHEADS * TSEQ * DKH];
__device__ __nv_bfloat16 g_Kl[(size_t)BHEADS * TSEQ * DKH];
__device__ __nv_bfloat16 g_Vh[(size_t)BHEADS * TSEQ * DKH];
__device__ __nv_bfloat16 g_Vl[(size_t)BHEADS * TSEQ * DKH];

// ---------------------------------------------------------------------------
// PTX helpers (sm_80-era ISA only)
// ---------------------------------------------------------------------------
__device__ __forceinline__ uint32_t smem_u32(const void* p) {
    uint32_t a;
    asm("{ .reg .u64 t; cvta.to.shared.u64 t, %1; cvt.u32.u64 %0, t; }"
        : "=r"(a) : "l"(p));
    return a;
}
__device__ __forceinline__ void cp16(uint32_t dst, const void* src) {
    asm volatile("cp.async.cg.shared.global [%0], [%1], 16;" :: "r"(dst), "l"(src));
}
__device__ __forceinline__ void cp_commit() {
    asm volatile("cp.async.commit_group;" ::: "memory");
}
template<int N> __device__ __forceinline__ void cp_wait() {
    asm volatile("cp.async.wait_group %0;" :: "n"(N) : "memory");
}
__device__ __forceinline__ void ldsm_x4(uint32_t* r, uint32_t addr) {
    asm volatile("ldmatrix.sync.aligned.m8n8.x4.shared.b16 {%0,%1,%2,%3}, [%4];"
        : "=r"(r[0]), "=r"(r[1]), "=r"(r[2]), "=r"(r[3]) : "r"(addr));
}
__device__ __forceinline__ void ldsm_x4_t(uint32_t* r, uint32_t addr) {
    asm volatile("ldmatrix.sync.aligned.m8n8.x4.trans.shared.b16 {%0,%1,%2,%3}, [%4];"
        : "=r"(r[0]), "=r"(r[1]), "=r"(r[2]), "=r"(r[3]) : "r"(addr));
}
__device__ __forceinline__ void mma16816(float* c, const uint32_t* a,
                                         uint32_t b0, uint32_t b1) {
    asm volatile("mma.sync.aligned.m16n8k16.row.col.f32.bf16.bf16.f32 "
        "{%0,%1,%2,%3}, {%4,%5,%6,%7}, {%8,%9}, {%0,%1,%2,%3};"
        : "+f"(c[0]), "+f"(c[1]), "+f"(c[2]), "+f"(c[3])
        : "r"(a[0]), "r"(a[1]), "r"(a[2]), "r"(a[3]), "r"(b0), "r"(b1));
}
__device__ __forceinline__ uint32_t packbf(float x, float y) {
    __nv_bfloat162 t = __floats2bfloat162_rn(x, y);
    return *(uint32_t*)&t;
}

// ---------------------------------------------------------------------------
// fp32 -> bf16-split for GEMM operands (extended-K layout)
// ---------------------------------------------------------------------------
__global__ void __launch_bounds__(256) convert_split(const float* __restrict__ X,
                                                     __nv_bfloat16* __restrict__ X3,
                                                     int rows, int act)
{
    size_t idx = (size_t)blockIdx.x * blockDim.x + threadIdx.x;
    size_t total = (size_t)rows * DMODEL / 4;
    if (idx >= total) return;
    const int m  = (int)(idx / (DMODEL / 4));
    const int k4 = (int)(idx % (DMODEL / 4)) * 4;
    float4 v = *(const float4*)(X + (size_t)m * DMODEL + k4);
    float f[4] = {v.x, v.y, v.z, v.w};
    __nv_bfloat16 hi[4], lo[4];
    #pragma unroll
    for (int j = 0; j < 4; j++) {
        hi[j] = __float2bfloat16_rn(f[j]);
        lo[j] = __float2bfloat16_rn(f[j] - __bfloat162float(hi[j]));
    }
    __nv_bfloat16* row = X3 + (size_t)m * K3;
    *(uint2*)(row + k4) = *(uint2*)hi;
    if (act) {
        *(uint2*)(row + 1024 + k4) = *(uint2*)hi;
        *(uint2*)(row + 2048 + k4) = *(uint2*)lo;
    } else {
        *(uint2*)(row + 1024 + k4) = *(uint2*)lo;
        *(uint2*)(row + 2048 + k4) = *(uint2*)hi;
    }
}

// fp32 -> bf16 hi/lo, same layout (for flash attention operands)
__global__ void __launch_bounds__(256) split_bf16(const float* __restrict__ X,
                                                  __nv_bfloat16* __restrict__ Xh,
                                                  __nv_bfloat16* __restrict__ Xl)
{
    size_t idx = (size_t)blockIdx.x * blockDim.x + threadIdx.x;  // float4 idx
    if (idx >= (size_t)BHEADS * TSEQ * DKH / 4) return;
    float4 v = *(const float4*)(X + idx * 4);
    float f[4] = {v.x, v.y, v.z, v.w};
    __nv_bfloat16 hi[4], lo[4];
    #pragma unroll
    for (int j = 0; j < 4; j++) {
        hi[j] = __float2bfloat16_rn(f[j]);
        lo[j] = __float2bfloat16_rn(f[j] - __bfloat162float(hi[j]));
    }
    *(uint2*)(Xh + idx * 4) = *(uint2*)hi;
    *(uint2*)(Xl + idx * 4) = *(uint2*)lo;
}

// ---------------------------------------------------------------------------
// HMMA GEMM (unchanged from round 3): C = A3 @ B3^T
// ---------------------------------------------------------------------------
#define BK   32
#define SSTR 40
#define NIT  (K3 / BK)   /* 96 */

__global__ void __launch_bounds__(256) gemm_mma(const __nv_bfloat16* __restrict__ A3,
                                                const __nv_bfloat16* __restrict__ B3,
                                                float* __restrict__ Cout,
                                                int headsplit)
{
    __shared__ __nv_bfloat16 sA[2][128 * SSTR];
    __shared__ __nv_bfloat16 sB[2][128 * SSTR];

    const int tid  = threadIdx.x;
    const int wid  = tid >> 5;
    const int lane = tid & 31;
    const int m0 = blockIdx.y * 128;
    const int n0 = blockIdx.x * 128;
    const int wm0 = (wid & 1) * 64;
    const int wn0 = (wid >> 1) * 32;

    const uint32_t sAu = smem_u32(sA);
    const uint32_t sBu = smem_u32(sB);
    const uint32_t stage_bytes = 128 * SSTR * 2;

    const int lrow = tid >> 1;
    const int lc0  = (tid & 1) * 2;
    const __nv_bfloat16* agp = A3 + (size_t)(m0 + lrow) * K3 + lc0 * 8;
    const __nv_bfloat16* bgp = B3 + (size_t)(n0 + lrow) * K3 + lc0 * 8;
    const uint32_t sAoff = sAu + ((uint32_t)lrow * SSTR + lc0 * 8) * 2;
    const uint32_t sBoff = sBu + ((uint32_t)lrow * SSTR + lc0 * 8) * 2;

    #define LOAD_STAGE(it, s) do {                                   \
        const int kc = (it) * BK;                                    \
        uint32_t so = (uint32_t)(s) * stage_bytes;                   \
        cp16(sAoff + so,      agp + kc);                             \
        cp16(sAoff + so + 16, agp + kc + 8);                         \
        cp16(sBoff + so,      bgp + kc);                             \
        cp16(sBoff + so + 16, bgp + kc + 8);                         \
        cp_commit();                                                 \
    } while (0)

    float acc[4][4][4];
    #pragma unroll
    for (int a = 0; a < 4; a++)
        #pragma unroll
        for (int b = 0; b < 4; b++)
            #pragma unroll
            for (int c = 0; c < 4; c++) acc[a][b][c] = 0.f;

    const uint32_t lrsel = lane & 15;
    const uint32_t lkoff = (lane >> 4) * 8;

    LOAD_STAGE(0, 0);

    for (int it = 0; it < NIT; it++) {
        const int s = it & 1;
        if (it + 1 < NIT) { LOAD_STAGE(it + 1, (it + 1) & 1); cp_wait<1>(); }
        else              { cp_wait<0>(); }
        __syncthreads();

        const uint32_t aBase = sAu + s * stage_bytes;
        const uint32_t bBase = sBu + s * stage_bytes;

        #pragma unroll
        for (int ks = 0; ks < 2; ks++) {
            const uint32_t koff = ks * 16 + lkoff;
            uint32_t af[4][4], bf[2][4];
            #pragma unroll
            for (int mt = 0; mt < 4; mt++)
                ldsm_x4(af[mt], aBase + (((uint32_t)(wm0 + mt * 16) + lrsel) * SSTR + koff) * 2);
            #pragma unroll
            for (int bp = 0; bp < 2; bp++)
                ldsm_x4(bf[bp], bBase + (((uint32_t)(wn0 + bp * 16) + lrsel) * SSTR + koff) * 2);
            #pragma unroll
            for (int mt = 0; mt < 4; mt++)
                #pragma unroll
                for (int ng = 0; ng < 4; ng++) {
                    const int bp = ng >> 1, lo = ng & 1;
                    mma16816(acc[mt][ng], af[mt], bf[bp][lo], bf[bp][lo + 2]);
                }
        }
        __syncthreads();
    }

    const int crow = lane >> 2;
    const int ccol = (lane & 3) * 2;
    #pragma unroll
    for (int mt = 0; mt < 4; mt++) {
        #pragma unroll
        for (int half = 0; half < 2; half++) {
            const int m = m0 + wm0 + mt * 16 + crow + half * 8;
            const int bb = m / TSEQ, t = m % TSEQ;
            #pragma unroll
            for (int ng = 0; ng < 4; ng++) {
                const int n = n0 + wn0 + ng * 8 + ccol;
                float2 o;
                o.x = acc[mt][ng][half * 2 + 0];
                o.y = acc[mt][ng][half * 2 + 1];
                if (headsplit) {
                    const int h = n >> 6, dk = n & 63;
                    *(float2*)(Cout + (((size_t)bb * NH + h) * TSEQ + t) * DKH + dk) = o;
                } else {
                    *(float2*)(Cout + (size_t)m * DMODEL + n) = o;
                }
            }
        }
    }
}

// ---------------------------------------------------------------------------
// Flash attention on mma.sync, bf16 3-term split.
// CTA: 128 q-rows x 64-key tiles, 8 warps (16 rows each). Grid (T/128, B*H).
// ---------------------------------------------------------------------------
#define QSTR   72                       /* smem row stride (elements) */
#define QBYTES (128 * QSTR * 2)         /* 18432 */
#define KVARR  (64 * QSTR * 2)          /* 9216 per array */
#define KVSTAGE (4 * KVARR)             /* Kh,Kl,Vh,Vl = 36864 */
#define FSMEM  (2 * QBYTES + 2 * KVSTAGE)  /* 110592 */

__global__ void __launch_bounds__(256) flash_mma()
{
    extern __shared__ char fsm[];
    const uint32_t sb = smem_u32(fsm);
    const uint32_t sQh = sb;
    const uint32_t sQl = sb + QBYTES;
    const uint32_t sKV0 = sb + 2 * QBYTES;

    const int tid  = threadIdx.x;
    const int wid  = tid >> 5;
    const int lane = tid & 31;
    const int bh = blockIdx.y;
    const int b  = bh >> 4;
    const int h  = bh & 15;
    const int q0 = blockIdx.x * 128;
    const int wm0 = wid * 16;

    const __nv_bfloat16* Qhg = g_Qh + (size_t)bh * TSEQ * DKH;
    const __nv_bfloat16* Qlg = g_Ql + (size_t)bh * TSEQ * DKH;
    const __nv_bfloat16* Khg = g_Kh + (size_t)bh * TSEQ * DKH;
    const __nv_bfloat16* Klg = g_Kl + (size_t)bh * TSEQ * DKH;
    const __nv_bfloat16* Vhg = g_Vh + (size_t)bh * TSEQ * DKH;
    const __nv_bfloat16* Vlg = g_Vl + (size_t)bh * TSEQ * DKH;

    // ---- Q tile load (Qh,Ql: 128 rows x 64 cols each) ----
    #pragma unroll
    for (int t = 0; t < 8; t++) {
        const int idx = tid + t * 256;           // 0..2047
        const int arr = idx >> 10;               // 0: Qh, 1: Ql
        const int rem = idx & 1023;
        const int row = rem >> 3;
        const int c8  = (rem & 7) << 3;
        const __nv_bfloat16* src = (arr ? Qlg : Qhg) + (size_t)(q0 + row) * DKH + c8;
        cp16(sb + arr * QBYTES + (uint32_t)(row * QSTR + c8) * 2, src);
    }
    cp_commit();

    const int nt = 2 * blockIdx.x + 2;  // key tiles

    // ---- KV tile loader ----
    #define LOAD_KV(kt, s) do {                                                  \
        const int k0l = (kt) * 64;                                               \
        _Pragma("unroll")                                                        \
        for (int t = 0; t < 8; t++) {                                            \
            const int idx = tid + t * 256;                                       \
            const int arr = idx >> 9;                                            \
            const int rem = idx & 511;                                           \
            const int row = rem >> 3;                                            \
            const int c8  = (rem & 7) << 3;                                      \
            const __nv_bfloat16* src =                                           \
                (arr == 0 ? Khg : arr == 1 ? Klg : arr == 2 ? Vhg : Vlg)         \
                + (size_t)(k0l + row) * DKH + c8;                                \
            cp16(sKV0 + (uint32_t)(s) * KVSTAGE + (uint32_t)arr * KVARR +        \
                 (uint32_t)(row * QSTR + c8) * 2, src);                          \
        }                                                                        \
        cp_commit();                                                             \
    } while (0)

    LOAD_KV(0, 0);

    float S[8][4], O[8][4];
    #pragma unroll
    for (int g = 0; g < 8; g++)
        #pragma unroll
        for (int e = 0; e < 4; e++) O[g][e] = 0.f;
    float m0r = -INFINITY, m1r = -INFINITY, l0r = 0.f, l1r = 0.f;

    const uint32_t lrsel = lane & 15;
    const uint32_t lkoff = (lane >> 4) * 8;
    const int row0 = q0 + wm0 + (lane >> 2);
    const int row1 = row0 + 8;
    const int cb   = 2 * (lane & 3);

    for (int it = 0; it < nt; it++) {
        const int k0 = it * 64;
        if (it + 1 < nt) { LOAD_KV(it + 1, (it + 1) & 1); cp_wait<1>(); }
        else             { cp_wait<0>(); }
        __syncthreads();

        const uint32_t kvb = sKV0 + (uint32_t)(it & 1) * KVSTAGE;
        const uint32_t bKh = kvb, bKl = kvb + KVARR;
        const uint32_t bVh = kvb + 2 * KVARR, bVl = kvb + 3 * KVARR;

        // ---- S = Qh*Kh + Qh*Kl + Ql*Kh ----
        #pragma unroll
        for (int g = 0; g < 8; g++)
            #pragma unroll
            for (int e = 0; e < 4; e++) S[g][e] = 0.f;

        #pragma unroll
        for (int ks = 0; ks < 4; ks++) {
            const uint32_t koff = ks * 16 + lkoff;
            uint32_t aqh[4], aql[4], kh[4][4], kl[4][4];
            ldsm_x4(aqh, sQh + (((uint32_t)wm0 + lrsel) * QSTR + koff) * 2);
            ldsm_x4(aql, sQl + (((uint32_t)wm0 + lrsel) * QSTR + koff) * 2);
            #pragma unroll
            for (int bp = 0; bp < 4; bp++) {
                ldsm_x4(kh[bp], bKh + (((uint32_t)(bp * 16) + lrsel) * QSTR + koff) * 2);
                ldsm_x4(kl[bp], bKl + (((uint32_t)(bp * 16) + lrsel) * QSTR + koff) * 2);
            }
            #pragma unroll
            for (int ng = 0; ng < 8; ng++) {
                const int bp = ng >> 1, lo = ng & 1;
                mma16816(S[ng], aqh, kh[bp][lo], kh[bp][lo + 2]);
                mma16816(S[ng], aqh, kl[bp][lo], kl[bp][lo + 2]);
                mma16816(S[ng], aql, kh[bp][lo], kh[bp][lo + 2]);
            }
        }

        // ---- scale + causal mask + online softmax ----
        float mx0 = -INFINITY, mx1 = -INFINITY;
        #pragma unroll
        for (int g = 0; g < 8; g++) {
            const int c0 = k0 + 8 * g + cb, c1 = c0 + 1;
            S[g][0] = (c0 <= row0) ? S[g][0] * 0.125f : -1e30f;
            S[g][1] = (c1 <= row0) ? S[g][1] * 0.125f : -1e30f;
            S[g][2] = (c0 <= row1) ? S[g][2] * 0.125f : -1e30f;
            S[g][3] = (c1 <= row1) ? S[g][3] * 0.125f : -1e30f;
            mx0 = fmaxf(mx0, fmaxf(S[g][0], S[g][1]));
            mx1 = fmaxf(mx1, fmaxf(S[g][2], S[g][3]));
        }
        mx0 = fmaxf(mx0, __shfl_xor_sync(0xffffffffu, mx0, 1));
        mx0 = fmaxf(mx0, __shfl_xor_sync(0xffffffffu, mx0, 2));
        mx1 = fmaxf(mx1, __shfl_xor_sync(0xffffffffu, mx1, 1));
        mx1 = fmaxf(mx1, __shfl_xor_sync(0xffffffffu, mx1, 2));

        const float mn0 = fmaxf(m0r, mx0), mn1 = fmaxf(m1r, mx1);
        const float al0 = __expf(m0r - mn0), al1 = __expf(m1r - mn1);
        float s0 = 0.f, s1 = 0.f;
        #pragma unroll
        for (int g = 0; g < 8; g++) {
            S[g][0] = __expf(S[g][0] - mn0);
            S[g][1] = __expf(S[g][1] - mn0);
            S[g][2] = __expf(S[g][2] - mn1);
            S[g][3] = __expf(S[g][3] - mn1);
            s0 += S[g][0] + S[g][1];
            s1 += S[g][2] + S[g][3];
        }
        s0 += __shfl_xor_sync(0xffffffffu, s0, 1);
        s0 += __shfl_xor_sync(0xffffffffu, s0, 2);
        s1 += __shfl_xor_sync(0xffffffffu, s1, 1);
        s1 += __shfl_xor_sync(0xffffffffu, s1, 2);
        l0r = l0r * al0 + s0; m0r = mn0;
        l1r = l1r * al1 + s1; m1r = mn1;
        #pragma unroll
        for (int g = 0; g < 8; g++) {
            O[g][0] *= al0; O[g][1] *= al0;
            O[g][2] *= al1; O[g][3] *= al1;
        }

        // ---- O += Ph*Vh + Ph*Vl + Pl*Vh ----
        const uint32_t vrow = (lane & 7) + ((lane >> 3) & 1) * 8;
        #pragma unroll
        for (int kk = 0; kk < 4; kk++) {
            uint32_t aph[4], apl[4];
            #pragma unroll
            for (int half = 0; half < 2; half++) {
                const int g = 2 * kk + half;
                float r0 = S[g][0], r1 = S[g][1], r2 = S[g][2], r3 = S[g][3];
                __nv_bfloat16 h0 = __float2bfloat16_rn(r0);
                __nv_bfloat16 h1 = __float2bfloat16_rn(r1);
                __nv_bfloat16 h2 = __float2bfloat16_rn(r2);
                __nv_bfloat16 h3 = __float2bfloat16_rn(r3);
                aph[2 * half + 0] = packbf(r0, r1);
                aph[2 * half + 1] = packbf(r2, r3);
                apl[2 * half + 0] = packbf(r0 - __bfloat162float(h0),
                                           r1 - __bfloat162float(h1));
                apl[2 * half + 1] = packbf(r2 - __bfloat162float(h2),
                                           r3 - __bfloat162float(h3));
            }
            #pragma unroll
            for (int j = 0; j < 4; j++) {
                uint32_t vh[4], vl[4];
                const uint32_t vaddr = ((uint32_t)(kk * 16) + vrow) * QSTR +
                                       (uint32_t)(j * 16) + lkoff;
                ldsm_x4_t(vh, bVh + vaddr * 2);
                ldsm_x4_t(vl, bVl + vaddr * 2);
                #pragma unroll
                for (int lo = 0; lo < 2; lo++) {
                    const int ng = 2 * j + lo;
                    mma16816(O[ng], aph, vh[2 * lo], vh[2 * lo + 1]);
                    mma16816(O[ng], aph, vl[2 * lo], vl[2 * lo + 1]);
                    mma16816(O[ng], apl, vh[2 * lo], vh[2 * lo + 1]);
                }
            }
        }
        __syncthreads();
    }

    // ---- epilogue ----
    const float il0 = 1.f / l0r, il1 = 1.f / l1r;
    #pragma unroll
    for (int g = 0; g < 8; g++) {
        const int dk = 8 * g + cb;
        float2 o0 = {O[g][0] * il0, O[g][1] * il0};
        float2 o1 = {O[g][2] * il1, O[g][3] * il1};
        *(float2*)(g_C + (size_t)(b * TSEQ + row0) * DMODEL + h * DKH + dk) = o0;
        *(float2*)(g_C + (size_t)(b * TSEQ + row1) * DMODEL + h * DKH + dk) = o1;
    }
    if ((lane & 3) == 0) {
        g_m[(size_t)bh * TSEQ + row0] = m0r;
        g_l[(size_t)bh * TSEQ + row0] = l0r;
        g_m[(size_t)bh * TSEQ + row1] = m1r;
        g_l[(size_t)bh * TSEQ + row1] = l1r;
    }
}

// ---------------------------------------------------------------------------
// attn_weights pass (optional, unchanged)
// ---------------------------------------------------------------------------
__global__ void __launch_bounds__(256) attn_weights(float* __restrict__ AW)
{
    const int bh = blockIdx.z;
    const int q0 = blockIdx.y << 6;
    const int k0 = blockIdx.x << 6;
    const int tid = threadIdx.x;
    const int tx = tid & 15;
    const int ty = tid >> 4;
    const size_t base = (size_t)bh * TSEQ * TSEQ;

    if (k0 > q0 + 63) {
        const float4 z = {0.f, 0.f, 0.f, 0.f};
        #pragma unroll
        for (int i = 0; i < 4; i++)
            *(float4*)(AW + base + (size_t)(q0 + ty * 4 + i) * TSEQ + k0 + tx * 4) = z;
        return;
    }

    __shared__ float Qst[64 * 68];
    __shared__ float Kst[64 * 68];
    const float* Qg = g_Q + (size_t)bh * TSEQ * DKH;
    const float* Kg = g_K + (size_t)bh * TSEQ * DKH;

    for (int i = tid; i < 64 * 16; i += 256) {
        const int r = i >> 4, c4 = (i & 15) << 2;
        float4 qv = *(const float4*)(Qg + (size_t)(q0 + r) * DKH + c4);
        Qst[(c4 + 0) * 68 + r] = qv.x;
        Qst[(c4 + 1) * 68 + r] = qv.y;
        Qst[(c4 + 2) * 68 + r] = qv.z;
        Qst[(c4 + 3) * 68 + r] = qv.w;
        float4 kv = *(const float4*)(Kg + (size_t)(k0 + r) * DKH + c4);
        Kst[(c4 + 0) * 68 + r] = kv.x;
        Kst[(c4 + 1) * 68 + r] = kv.y;
        Kst[(c4 + 2) * 68 + r] = kv.z;
        Kst[(c4 + 3) * 68 + r] = kv.w;
    }
    __syncthreads();

    float S[4][4] = {};
    #pragma unroll 8
    for (int d = 0; d < 64; d++) {
        float4 qa = *(const float4*)&Qst[d * 68 + ty * 4];
        float4 kb = *(const float4*)&Kst[d * 68 + tx * 4];
        float qv[4] = {qa.x, qa.y, qa.z, qa.w};
        float kv[4] = {kb.x, kb.y, kb.z, kb.w};
        #pragma unroll
        for (int i = 0; i < 4; i++)
            #pragma unroll
            for (int j = 0; j < 4; j++)
                S[i][j] += qv[i] * kv[j];
    }

    #pragma unroll
    for (int i = 0; i < 4; i++) {
        const int q = q0 + ty * 4 + i;
        const float mm = g_m[(size_t)bh * TSEQ + q];
        const float il = 1.f / g_l[(size_t)bh * TSEQ + q];
        float4 w4;
        float w[4];
        #pragma unroll
        for (int j = 0; j < 4; j++) {
            const int k = k0 + tx * 4 + j;
            w[j] = (k <= q) ? expf(S[i][j] * 0.125f - mm) * il : 0.f;
        }
        w4.x = w[0]; w4.y = w[1]; w4.z = w[2]; w4.w = w[3];
        *(float4*)(AW + base + (size_t)q * TSEQ + k0 + tx * 4) = w4;
    }
}

// ---------------------------------------------------------------------------
extern "C" void kernel_launch(void* const* d_in, const int* in_sizes, int n_in,
                              void* d_out, int out_size)
{
    const float* q  = (const float*)d_in[0];
    const float* k  = (const float*)d_in[1];
    const float* v  = (const float*)d_in[2];
    // d_in[3] = mask (causal by construction; applied analytically)
    const float* Wq = (const float*)d_in[4];
    const float* Wk = (const float*)d_in[5];
    const float* Wv = (const float*)d_in[6];
    const float* Wo = (const float*)d_in[7];
    float* out = (float*)d_out;

    void *pQ, *pK, *pV, *pC, *pA3, *pW3;
    void *pQh, *pQl, *pKh, *pKl, *pVh, *pVl;
    cudaGetSymbolAddress(&pQ, g_Q);
    cudaGetSymbolAddress(&pK, g_K);
    cudaGetSymbolAddress(&pV, g_V);
    cudaGetSymbolAddress(&pC, g_C);
    cudaGetSymbolAddress(&pA3, g_A3);
    cudaGetSymbolAddress(&pW3, g_W3);
    cudaGetSymbolAddress(&pQh, g_Qh);
    cudaGetSymbolAddress(&pQl, g_Ql);
    cudaGetSymbolAddress(&pKh, g_Kh);
    cudaGetSymbolAddress(&pKl, g_Kl);
    cudaGetSymbolAddress(&pVh, g_Vh);
    cudaGetSymbolAddress(&pVl, g_Vl);
    __nv_bfloat16* A3 = (__nv_bfloat16*)pA3;
    __nv_bfloat16* W3 = (__nv_bfloat16*)pW3;

    const int cva = (MROWS * DMODEL / 4 + 255) / 256;
    const int cvw = (DMODEL * DMODEL / 4 + 255) / 256;
    const int cvs = (BHEADS * TSEQ * DKH / 4 + 255) / 256;
    const dim3 gg(DMODEL / 128, MROWS / 128);

    convert_split<<<cva, 256>>>(q, A3, MROWS, 1);
    convert_split<<<cvw, 256>>>(Wq, W3, DMODEL, 0);
    gemm_mma<<<gg, 256>>>(A3, W3, (float*)pQ, 1);

    convert_split<<<cva, 256>>>(k, A3, MROWS, 1);
    convert_split<<<cvw, 256>>>(Wk, W3, DMODEL, 0);
    gemm_mma<<<gg, 256>>>(A3, W3, (float*)pK, 1);

    convert_split<<<cva, 256>>>(v, A3, MROWS, 1);
    convert_split<<<cvw, 256>>>(Wv, W3, DMODEL, 0);
    gemm_mma<<<gg, 256>>>(A3, W3, (float*)pV, 1);

    split_bf16<<<cvs, 256>>>((const float*)pQ, (__nv_bfloat16*)pQh, (__nv_bfloat16*)pQl);
    split_bf16<<<cvs, 256>>>((const float*)pK, (__nv_bfloat16*)pKh, (__nv_bfloat16*)pKl);
    split_bf16<<<cvs, 256>>>((const float*)pV, (__nv_bfloat16*)pVh, (__nv_bfloat16*)pVl);

    cudaFuncSetAttribute(flash_mma, cudaFuncAttributeMaxDynamicSharedMemorySize, FSMEM);
    flash_mma<<<dim3(TSEQ / 128, BHEADS), 256, FSMEM>>>();

    convert_split<<<cva, 256>>>((const float*)pC, A3, MROWS, 1);
    convert_split<<<cvw, 256>>>(Wo, W3, DMODEL, 0);
    gemm_mma<<<gg, 256>>>(A3, W3, out, 0);

    const long long n_out = (long long)MROWS * DMODEL;
    const long long n_aw  = (long long)BHEADS * TSEQ * TSEQ;
    if ((long long)out_size >= n_out + n_aw) {
        attn_weights<<<dim3(TSEQ / 64, TSEQ / 64, BHEADS), 256>>>(out + (size_t)n_out);
    }
}

// round 5
// speedup vs baseline: 1.9680x; 1.0260x over previous
#include <cuda_runtime.h>
#include <cuda_bf16.h>
#include <math.h>
#include <stdint.h>

#define BATCH  2
#define TSEQ   2048
#define DMODEL 1024
#define NH     16
#define DKH    64
#define MROWS  (BATCH * TSEQ)   /* 4096 */
#define BHEADS (BATCH * NH)     /* 32 */
#define K3     3072             /* extended K for bf16-split GEMM */

// ---------------- scratch (device globals: no allocations allowed) ----------
__device__ float g_Q[(size_t)BHEADS * TSEQ * DKH];   // (B,H,T,DK) fp32
__device__ float g_K[(size_t)BHEADS * TSEQ * DKH];
__device__ float g_V[(size_t)BHEADS * TSEQ * DKH];
__device__ float g_C[(size_t)MROWS * DMODEL];        // combined attn out (B,T,D)
__device__ float g_m[(size_t)BHEADS * TSEQ];         // per-row softmax max
__device__ float g_l[(size_t)BHEADS * TSEQ];         // per-row softmax denom
__device__ __nv_bfloat16 g_A3[(size_t)MROWS * K3];   // [hi|hi|lo] activations
__device__ __nv_bfloat16 g_W3[(size_t)DMODEL * K3];  // [hi|lo|hi] weights
__device__ __nv_bfloat16 g_Qh[(size_t)BHEADS * TSEQ * DKH];
__device__ __nv_bfloat16 g_Ql[(size_t)BHEADS * TSEQ * DKH];
__device__ __nv_bfloat16 g_Kh[(size_t)BHEADS * TSEQ * DKH];
__device__ __nv_bfloat16 g_Kl[(size_t)BHEADS * TSEQ * DKH];
__device__ __nv_bfloat16 g_Vh[(size_t)BHEADS * TSEQ * DKH];
__device__ __nv_bfloat16 g_Vl[(size_t)BHEADS * TSEQ * DKH];

// ---------------------------------------------------------------------------
// PTX helpers (sm_80-era ISA only)
// ---------------------------------------------------------------------------
__device__ __forceinline__ uint32_t smem_u32(const void* p) {
    uint32_t a;
    asm("{ .reg .u64 t; cvta.to.shared.u64 t, %1; cvt.u32.u64 %0, t; }"
        : "=r"(a) : "l"(p));
    return a;
}
__device__ __forceinline__ void cp16(uint32_t dst, const void* src) {
    asm volatile("cp.async.cg.shared.global [%0], [%1], 16;" :: "r"(dst), "l"(src));
}
__device__ __forceinline__ void cp_commit() {
    asm volatile("cp.async.commit_group;" ::: "memory");
}
template<int N> __device__ __forceinline__ void cp_wait() {
    asm volatile("cp.async.wait_group %0;" :: "n"(N) : "memory");
}
__device__ __forceinline__ void ldsm_x4(uint32_t* r, uint32_t addr) {
    asm volatile("ldmatrix.sync.aligned.m8n8.x4.shared.b16 {%0,%1,%2,%3}, [%4];"
        : "=r"(r[0]), "=r"(r[1]), "=r"(r[2]), "=r"(r[3]) : "r"(addr));
}
__device__ __forceinline__ void ldsm_x4_t(uint32_t* r, uint32_t addr) {
    asm volatile("ldmatrix.sync.aligned.m8n8.x4.trans.shared.b16 {%0,%1,%2,%3}, [%4];"
        : "=r"(r[0]), "=r"(r[1]), "=r"(r[2]), "=r"(r[3]) : "r"(addr));
}
__device__ __forceinline__ void mma16816(float* c, const uint32_t* a,
                                         uint32_t b0, uint32_t b1) {
    asm volatile("mma.sync.aligned.m16n8k16.row.col.f32.bf16.bf16.f32 "
        "{%0,%1,%2,%3}, {%4,%5,%6,%7}, {%8,%9}, {%0,%1,%2,%3};"
        : "+f"(c[0]), "+f"(c[1]), "+f"(c[2]), "+f"(c[3])
        : "r"(a[0]), "r"(a[1]), "r"(a[2]), "r"(a[3]), "r"(b0), "r"(b1));
}
__device__ __forceinline__ uint32_t packbf(float x, float y) {
    __nv_bfloat162 t = __floats2bfloat162_rn(x, y);
    return *(uint32_t*)&t;
}

// ---------------------------------------------------------------------------
// fp32 -> bf16-split for GEMM operands (extended-K layout)
// ---------------------------------------------------------------------------
__global__ void __launch_bounds__(256) convert_split(const float* __restrict__ X,
                                                     __nv_bfloat16* __restrict__ X3,
                                                     int rows, int act)
{
    size_t idx = (size_t)blockIdx.x * blockDim.x + threadIdx.x;
    size_t total = (size_t)rows * DMODEL / 4;
    if (idx >= total) return;
    const int m  = (int)(idx / (DMODEL / 4));
    const int k4 = (int)(idx % (DMODEL / 4)) * 4;
    float4 v = *(const float4*)(X + (size_t)m * DMODEL + k4);
    float f[4] = {v.x, v.y, v.z, v.w};
    __nv_bfloat16 hi[4], lo[4];
    #pragma unroll
    for (int j = 0; j < 4; j++) {
        hi[j] = __float2bfloat16_rn(f[j]);
        lo[j] = __float2bfloat16_rn(f[j] - __bfloat162float(hi[j]));
    }
    __nv_bfloat16* row = X3 + (size_t)m * K3;
    *(uint2*)(row + k4) = *(uint2*)hi;
    if (act) {
        *(uint2*)(row + 1024 + k4) = *(uint2*)hi;
        *(uint2*)(row + 2048 + k4) = *(uint2*)lo;
    } else {
        *(uint2*)(row + 1024 + k4) = *(uint2*)lo;
        *(uint2*)(row + 2048 + k4) = *(uint2*)hi;
    }
}

// fp32 -> bf16 hi/lo (for flash attention operands)
__global__ void __launch_bounds__(256) split_bf16(const float* __restrict__ X,
                                                  __nv_bfloat16* __restrict__ Xh,
                                                  __nv_bfloat16* __restrict__ Xl)
{
    size_t idx = (size_t)blockIdx.x * blockDim.x + threadIdx.x;  // float4 idx
    if (idx >= (size_t)BHEADS * TSEQ * DKH / 4) return;
    float4 v = *(const float4*)(X + idx * 4);
    float f[4] = {v.x, v.y, v.z, v.w};
    __nv_bfloat16 hi[4], lo[4];
    #pragma unroll
    for (int j = 0; j < 4; j++) {
        hi[j] = __float2bfloat16_rn(f[j]);
        lo[j] = __float2bfloat16_rn(f[j] - __bfloat162float(hi[j]));
    }
    *(uint2*)(Xh + idx * 4) = *(uint2*)hi;
    *(uint2*)(Xl + idx * 4) = *(uint2*)lo;
}

// ---------------------------------------------------------------------------
// HMMA GEMM, 4-stage cp.async pipeline: C = A3 @ B3^T
// CTA 128x128, BK=32, 256 threads (8 warps 2Mx4N), warp tile 64x32.
// One __syncthreads per K-iteration.
// ---------------------------------------------------------------------------
#define BK     32
#define SSTR   40
#define NIT    (K3 / BK)          /* 96 */
#define NSTAGE 4
#define ASTG   (128 * SSTR * 2)   /* 10240 B per operand per stage */
#define STG    (2 * ASTG)         /* 20480 */
#define GSMEM  (NSTAGE * STG)     /* 81920 */

__global__ void __launch_bounds__(256, 2) gemm_mma(const __nv_bfloat16* __restrict__ A3,
                                                   const __nv_bfloat16* __restrict__ B3,
                                                   float* __restrict__ Cout,
                                                   int headsplit)
{
    extern __shared__ char gsm[];
    const uint32_t sb = smem_u32(gsm);

    const int tid  = threadIdx.x;
    const int wid  = tid >> 5;
    const int lane = tid & 31;
    const int m0 = blockIdx.y * 128;
    const int n0 = blockIdx.x * 128;
    const int wm0 = (wid & 1) * 64;
    const int wn0 = (wid >> 1) * 32;

    // loader mapping: each thread one row, two 16B chunks per operand
    const int lrow = tid >> 1;
    const int lc0  = (tid & 1) * 2;
    const __nv_bfloat16* agp = A3 + (size_t)(m0 + lrow) * K3 + lc0 * 8;
    const __nv_bfloat16* bgp = B3 + (size_t)(n0 + lrow) * K3 + lc0 * 8;
    const uint32_t sAoff = sb + ((uint32_t)lrow * SSTR + lc0 * 8) * 2;
    const uint32_t sBoff = sAoff + ASTG;

    #define LOAD_STAGE(it, s) do {                                   \
        const int kc = (it) * BK;                                    \
        uint32_t so = (uint32_t)(s) * STG;                           \
        cp16(sAoff + so,      agp + kc);                             \
        cp16(sAoff + so + 16, agp + kc + 8);                         \
        cp16(sBoff + so,      bgp + kc);                             \
        cp16(sBoff + so + 16, bgp + kc + 8);                         \
        cp_commit();                                                 \
    } while (0)

    float acc[4][4][4];
    #pragma unroll
    for (int a = 0; a < 4; a++)
        #pragma unroll
        for (int b = 0; b < 4; b++)
            #pragma unroll
            for (int c = 0; c < 4; c++) acc[a][b][c] = 0.f;

    const uint32_t lrsel = lane & 15;
    const uint32_t lkoff = (lane >> 4) * 8;

    // prologue: stages 0..2 in flight (3 groups)
    LOAD_STAGE(0, 0);
    LOAD_STAGE(1, 1);
    LOAD_STAGE(2, 2);

    for (int it = 0; it < NIT; it++) {
        const int s = it & (NSTAGE - 1);
        cp_wait<NSTAGE - 2>();      // stage `it` resident (2 newer groups pending)
        __syncthreads();            // all warps done with slot being overwritten below
        if (it + 3 < NIT) LOAD_STAGE(it + 3, (it + 3) & (NSTAGE - 1));
        else              cp_commit();   // empty group keeps wait-count uniform

        const uint32_t aBase = sb + (uint32_t)s * STG;
        const uint32_t bBase = aBase + ASTG;

        #pragma unroll
        for (int ks = 0; ks < 2; ks++) {
            const uint32_t koff = ks * 16 + lkoff;
            uint32_t af[4][4], bf[2][4];
            #pragma unroll
            for (int mt = 0; mt < 4; mt++)
                ldsm_x4(af[mt], aBase + (((uint32_t)(wm0 + mt * 16) + lrsel) * SSTR + koff) * 2);
            #pragma unroll
            for (int bp = 0; bp < 2; bp++)
                ldsm_x4(bf[bp], bBase + (((uint32_t)(wn0 + bp * 16) + lrsel) * SSTR + koff) * 2);
            #pragma unroll
            for (int mt = 0; mt < 4; mt++)
                #pragma unroll
                for (int ng = 0; ng < 4; ng++) {
                    const int bp = ng >> 1, lo = ng & 1;
                    mma16816(acc[mt][ng], af[mt], bf[bp][lo], bf[bp][lo + 2]);
                }
        }
    }

    const int crow = lane >> 2;
    const int ccol = (lane & 3) * 2;
    #pragma unroll
    for (int mt = 0; mt < 4; mt++) {
        #pragma unroll
        for (int half = 0; half < 2; half++) {
            const int m = m0 + wm0 + mt * 16 + crow + half * 8;
            const int bb = m / TSEQ, t = m % TSEQ;
            #pragma unroll
            for (int ng = 0; ng < 4; ng++) {
                const int n = n0 + wn0 + ng * 8 + ccol;
                float2 o;
                o.x = acc[mt][ng][half * 2 + 0];
                o.y = acc[mt][ng][half * 2 + 1];
                if (headsplit) {
                    const int h = n >> 6, dk = n & 63;
                    *(float2*)(Cout + (((size_t)bb * NH + h) * TSEQ + t) * DKH + dk) = o;
                } else {
                    *(float2*)(Cout + (size_t)m * DMODEL + n) = o;
                }
            }
        }
    }
}

// ---------------------------------------------------------------------------
// Flash attention on mma.sync, bf16 3-term split (unchanged from round 4).
// ---------------------------------------------------------------------------
#define QSTR   72
#define QBYTES (128 * QSTR * 2)
#define KVARR  (64 * QSTR * 2)
#define KVSTAGE (4 * KVARR)
#define FSMEM  (2 * QBYTES + 2 * KVSTAGE)

__global__ void __launch_bounds__(256) flash_mma()
{
    extern __shared__ char fsm[];
    const uint32_t sb = smem_u32(fsm);
    const uint32_t sQh = sb;
    const uint32_t sQl = sb + QBYTES;
    const uint32_t sKV0 = sb + 2 * QBYTES;

    const int tid  = threadIdx.x;
    const int wid  = tid >> 5;
    const int lane = tid & 31;
    const int bh = blockIdx.y;
    const int b  = bh >> 4;
    const int h  = bh & 15;
    const int q0 = blockIdx.x * 128;
    const int wm0 = wid * 16;

    const __nv_bfloat16* Qhg = g_Qh + (size_t)bh * TSEQ * DKH;
    const __nv_bfloat16* Qlg = g_Ql + (size_t)bh * TSEQ * DKH;
    const __nv_bfloat16* Khg = g_Kh + (size_t)bh * TSEQ * DKH;
    const __nv_bfloat16* Klg = g_Kl + (size_t)bh * TSEQ * DKH;
    const __nv_bfloat16* Vhg = g_Vh + (size_t)bh * TSEQ * DKH;
    const __nv_bfloat16* Vlg = g_Vl + (size_t)bh * TSEQ * DKH;

    #pragma unroll
    for (int t = 0; t < 8; t++) {
        const int idx = tid + t * 256;
        const int arr = idx >> 10;
        const int rem = idx & 1023;
        const int row = rem >> 3;
        const int c8  = (rem & 7) << 3;
        const __nv_bfloat16* src = (arr ? Qlg : Qhg) + (size_t)(q0 + row) * DKH + c8;
        cp16(sb + arr * QBYTES + (uint32_t)(row * QSTR + c8) * 2, src);
    }
    cp_commit();

    const int nt = 2 * blockIdx.x + 2;

    #define LOAD_KV(kt, s) do {                                                  \
        const int k0l = (kt) * 64;                                               \
        _Pragma("unroll")                                                        \
        for (int t = 0; t < 8; t++) {                                            \
            const int idx = tid + t * 256;                                       \
            const int arr = idx >> 9;                                            \
            const int rem = idx & 511;                                           \
            const int row = rem >> 3;                                            \
            const int c8  = (rem & 7) << 3;                                      \
            const __nv_bfloat16* src =                                           \
                (arr == 0 ? Khg : arr == 1 ? Klg : arr == 2 ? Vhg : Vlg)         \
                + (size_t)(k0l + row) * DKH + c8;                                \
            cp16(sKV0 + (uint32_t)(s) * KVSTAGE + (uint32_t)arr * KVARR +        \
                 (uint32_t)(row * QSTR + c8) * 2, src);                          \
        }                                                                        \
        cp_commit();                                                             \
    } while (0)

    LOAD_KV(0, 0);

    float S[8][4], O[8][4];
    #pragma unroll
    for (int g = 0; g < 8; g++)
        #pragma unroll
        for (int e = 0; e < 4; e++) O[g][e] = 0.f;
    float m0r = -INFINITY, m1r = -INFINITY, l0r = 0.f, l1r = 0.f;

    const uint32_t lrsel = lane & 15;
    const uint32_t lkoff = (lane >> 4) * 8;
    const int row0 = q0 + wm0 + (lane >> 2);
    const int row1 = row0 + 8;
    const int cb   = 2 * (lane & 3);

    for (int it = 0; it < nt; it++) {
        const int k0 = it * 64;
        if (it + 1 < nt) { LOAD_KV(it + 1, (it + 1) & 1); cp_wait<1>(); }
        else             { cp_wait<0>(); }
        __syncthreads();

        const uint32_t kvb = sKV0 + (uint32_t)(it & 1) * KVSTAGE;
        const uint32_t bKh = kvb, bKl = kvb + KVARR;
        const uint32_t bVh = kvb + 2 * KVARR, bVl = kvb + 3 * KVARR;

        #pragma unroll
        for (int g = 0; g < 8; g++)
            #pragma unroll
            for (int e = 0; e < 4; e++) S[g][e] = 0.f;

        #pragma unroll
        for (int ks = 0; ks < 4; ks++) {
            const uint32_t koff = ks * 16 + lkoff;
            uint32_t aqh[4], aql[4], kh[4][4], kl[4][4];
            ldsm_x4(aqh, sQh + (((uint32_t)wm0 + lrsel) * QSTR + koff) * 2);
            ldsm_x4(aql, sQl + (((uint32_t)wm0 + lrsel) * QSTR + koff) * 2);
            #pragma unroll
            for (int bp = 0; bp < 4; bp++) {
                ldsm_x4(kh[bp], bKh + (((uint32_t)(bp * 16) + lrsel) * QSTR + koff) * 2);
                ldsm_x4(kl[bp], bKl + (((uint32_t)(bp * 16) + lrsel) * QSTR + koff) * 2);
            }
            #pragma unroll
            for (int ng = 0; ng < 8; ng++) {
                const int bp = ng >> 1, lo = ng & 1;
                mma16816(S[ng], aqh, kh[bp][lo], kh[bp][lo + 2]);
                mma16816(S[ng], aqh, kl[bp][lo], kl[bp][lo + 2]);
                mma16816(S[ng], aql, kh[bp][lo], kh[bp][lo + 2]);
            }
        }

        float mx0 = -INFINITY, mx1 = -INFINITY;
        #pragma unroll
        for (int g = 0; g < 8; g++) {
            const int c0 = k0 + 8 * g + cb, c1 = c0 + 1;
            S[g][0] = (c0 <= row0) ? S[g][0] * 0.125f : -1e30f;
            S[g][1] = (c1 <= row0) ? S[g][1] * 0.125f : -1e30f;
            S[g][2] = (c0 <= row1) ? S[g][2] * 0.125f : -1e30f;
            S[g][3] = (c1 <= row1) ? S[g][3] * 0.125f : -1e30f;
            mx0 = fmaxf(mx0, fmaxf(S[g][0], S[g][1]));
            mx1 = fmaxf(mx1, fmaxf(S[g][2], S[g][3]));
        }
        mx0 = fmaxf(mx0, __shfl_xor_sync(0xffffffffu, mx0, 1));
        mx0 = fmaxf(mx0, __shfl_xor_sync(0xffffffffu, mx0, 2));
        mx1 = fmaxf(mx1, __shfl_xor_sync(0xffffffffu, mx1, 1));
        mx1 = fmaxf(mx1, __shfl_xor_sync(0xffffffffu, mx1, 2));

        const float mn0 = fmaxf(m0r, mx0), mn1 = fmaxf(m1r, mx1);
        const float al0 = __expf(m0r - mn0), al1 = __expf(m1r - mn1);
        float s0 = 0.f, s1 = 0.f;
        #pragma unroll
        for (int g = 0; g < 8; g++) {
            S[g][0] = __expf(S[g][0] - mn0);
            S[g][1] = __expf(S[g][1] - mn0);
            S[g][2] = __expf(S[g][2] - mn1);
            S[g][3] = __expf(S[g][3] - mn1);
            s0 += S[g][0] + S[g][1];
            s1 += S[g][2] + S[g][3];
        }
        s0 += __shfl_xor_sync(0xffffffffu, s0, 1);
        s0 += __shfl_xor_sync(0xffffffffu, s0, 2);
        s1 += __shfl_xor_sync(0xffffffffu, s1, 1);
        s1 += __shfl_xor_sync(0xffffffffu, s1, 2);
        l0r = l0r * al0 + s0; m0r = mn0;
        l1r = l1r * al1 + s1; m1r = mn1;
        #pragma unroll
        for (int g = 0; g < 8; g++) {
            O[g][0] *= al0; O[g][1] *= al0;
            O[g][2] *= al1; O[g][3] *= al1;
        }

        const uint32_t vrow = (lane & 7) + ((lane >> 3) & 1) * 8;
        #pragma unroll
        for (int kk = 0; kk < 4; kk++) {
            uint32_t aph[4], apl[4];
            #pragma unroll
            for (int half = 0; half < 2; half++) {
                const int g = 2 * kk + half;
                float r0 = S[g][0], r1 = S[g][1], r2 = S[g][2], r3 = S[g][3];
                __nv_bfloat16 h0 = __float2bfloat16_rn(r0);
                __nv_bfloat16 h1 = __float2bfloat16_rn(r1);
                __nv_bfloat16 h2 = __float2bfloat16_rn(r2);
                __nv_bfloat16 h3 = __float2bfloat16_rn(r3);
                aph[2 * half + 0] = packbf(r0, r1);
                aph[2 * half + 1] = packbf(r2, r3);
                apl[2 * half + 0] = packbf(r0 - __bfloat162float(h0),
                                           r1 - __bfloat162float(h1));
                apl[2 * half + 1] = packbf(r2 - __bfloat162float(h2),
                                           r3 - __bfloat162float(h3));
            }
            #pragma unroll
            for (int j = 0; j < 4; j++) {
                uint32_t vh[4], vl[4];
                const uint32_t vaddr = ((uint32_t)(kk * 16) + vrow) * QSTR +
                                       (uint32_t)(j * 16) + lkoff;
                ldsm_x4_t(vh, bVh + vaddr * 2);
                ldsm_x4_t(vl, bVl + vaddr * 2);
                #pragma unroll
                for (int lo = 0; lo < 2; lo++) {
                    const int ng = 2 * j + lo;
                    mma16816(O[ng], aph, vh[2 * lo], vh[2 * lo + 1]);
                    mma16816(O[ng], aph, vl[2 * lo], vl[2 * lo + 1]);
                    mma16816(O[ng], apl, vh[2 * lo], vh[2 * lo + 1]);
                }
            }
        }
        __syncthreads();
    }

    const float il0 = 1.f / l0r, il1 = 1.f / l1r;
    #pragma unroll
    for (int g = 0; g < 8; g++) {
        const int dk = 8 * g + cb;
        float2 o0 = {O[g][0] * il0, O[g][1] * il0};
        float2 o1 = {O[g][2] * il1, O[g][3] * il1};
        *(float2*)(g_C + (size_t)(b * TSEQ + row0) * DMODEL + h * DKH + dk) = o0;
        *(float2*)(g_C + (size_t)(b * TSEQ + row1) * DMODEL + h * DKH + dk) = o1;
    }
    if ((lane & 3) == 0) {
        g_m[(size_t)bh * TSEQ + row0] = m0r;
        g_l[(size_t)bh * TSEQ + row0] = l0r;
        g_m[(size_t)bh * TSEQ + row1] = m1r;
        g_l[(size_t)bh * TSEQ + row1] = l1r;
    }
}

// ---------------------------------------------------------------------------
// attn_weights pass (optional, unchanged)
// ---------------------------------------------------------------------------
__global__ void __launch_bounds__(256) attn_weights(float* __restrict__ AW)
{
    const int bh = blockIdx.z;
    const int q0 = blockIdx.y << 6;
    const int k0 = blockIdx.x << 6;
    const int tid = threadIdx.x;
    const int tx = tid & 15;
    const int ty = tid >> 4;
    const size_t base = (size_t)bh * TSEQ * TSEQ;

    if (k0 > q0 + 63) {
        const float4 z = {0.f, 0.f, 0.f, 0.f};
        #pragma unroll
        for (int i = 0; i < 4; i++)
            *(float4*)(AW + base + (size_t)(q0 + ty * 4 + i) * TSEQ + k0 + tx * 4) = z;
        return;
    }

    __shared__ float Qst[64 * 68];
    __shared__ float Kst[64 * 68];
    const float* Qg = g_Q + (size_t)bh * TSEQ * DKH;
    const float* Kg = g_K + (size_t)bh * TSEQ * DKH;

    for (int i = tid; i < 64 * 16; i += 256) {
        const int r = i >> 4, c4 = (i & 15) << 2;
        float4 qv = *(const float4*)(Qg + (size_t)(q0 + r) * DKH + c4);
        Qst[(c4 + 0) * 68 + r] = qv.x;
        Qst[(c4 + 1) * 68 + r] = qv.y;
        Qst[(c4 + 2) * 68 + r] = qv.z;
        Qst[(c4 + 3) * 68 + r] = qv.w;
        float4 kv = *(const float4*)(Kg + (size_t)(k0 + r) * DKH + c4);
        Kst[(c4 + 0) * 68 + r] = kv.x;
        Kst[(c4 + 1) * 68 + r] = kv.y;
        Kst[(c4 + 2) * 68 + r] = kv.z;
        Kst[(c4 + 3) * 68 + r] = kv.w;
    }
    __syncthreads();

    float S[4][4] = {};
    #pragma unroll 8
    for (int d = 0; d < 64; d++) {
        float4 qa = *(const float4*)&Qst[d * 68 + ty * 4];
        float4 kb = *(const float4*)&Kst[d * 68 + tx * 4];
        float qv[4] = {qa.x, qa.y, qa.z, qa.w};
        float kv[4] = {kb.x, kb.y, kb.z, kb.w};
        #pragma unroll
        for (int i = 0; i < 4; i++)
            #pragma unroll
            for (int j = 0; j < 4; j++)
                S[i][j] += qv[i] * kv[j];
    }

    #pragma unroll
    for (int i = 0; i < 4; i++) {
        const int q = q0 + ty * 4 + i;
        const float mm = g_m[(size_t)bh * TSEQ + q];
        const float il = 1.f / g_l[(size_t)bh * TSEQ + q];
        float4 w4;
        float w[4];
        #pragma unroll
        for (int j = 0; j < 4; j++) {
            const int k = k0 + tx * 4 + j;
            w[j] = (k <= q) ? expf(S[i][j] * 0.125f - mm) * il : 0.f;
        }
        w4.x = w[0]; w4.y = w[1]; w4.z = w[2]; w4.w = w[3];
        *(float4*)(AW + base + (size_t)q * TSEQ + k0 + tx * 4) = w4;
    }
}

// ---------------------------------------------------------------------------
extern "C" void kernel_launch(void* const* d_in, const int* in_sizes, int n_in,
                              void* d_out, int out_size)
{
    const float* q  = (const float*)d_in[0];
    const float* k  = (const float*)d_in[1];
    const float* v  = (const float*)d_in[2];
    // d_in[3] = mask (causal by construction; applied analytically)
    const float* Wq = (const float*)d_in[4];
    const float* Wk = (const float*)d_in[5];
    const float* Wv = (const float*)d_in[6];
    const float* Wo = (const float*)d_in[7];
    float* out = (float*)d_out;

    void *pQ, *pK, *pV, *pC, *pA3, *pW3;
    void *pQh, *pQl, *pKh, *pKl, *pVh, *pVl;
    cudaGetSymbolAddress(&pQ, g_Q);
    cudaGetSymbolAddress(&pK, g_K);
    cudaGetSymbolAddress(&pV, g_V);
    cudaGetSymbolAddress(&pC, g_C);
    cudaGetSymbolAddress(&pA3, g_A3);
    cudaGetSymbolAddress(&pW3, g_W3);
    cudaGetSymbolAddress(&pQh, g_Qh);
    cudaGetSymbolAddress(&pQl, g_Ql);
    cudaGetSymbolAddress(&pKh, g_Kh);
    cudaGetSymbolAddress(&pKl, g_Kl);
    cudaGetSymbolAddress(&pVh, g_Vh);
    cudaGetSymbolAddress(&pVl, g_Vl);
    __nv_bfloat16* A3 = (__nv_bfloat16*)pA3;
    __nv_bfloat16* W3 = (__nv_bfloat16*)pW3;

    cudaFuncSetAttribute(gemm_mma, cudaFuncAttributeMaxDynamicSharedMemorySize, GSMEM);

    const int cva = (MROWS * DMODEL / 4 + 255) / 256;
    const int cvw = (DMODEL * DMODEL / 4 + 255) / 256;
    const int cvs = (BHEADS * TSEQ * DKH / 4 + 255) / 256;
    const dim3 gg(DMODEL / 128, MROWS / 128);

    convert_split<<<cva, 256>>>(q, A3, MROWS, 1);
    convert_split<<<cvw, 256>>>(Wq, W3, DMODEL, 0);
    gemm_mma<<<gg, 256, GSMEM>>>(A3, W3, (float*)pQ, 1);

    convert_split<<<cva, 256>>>(k, A3, MROWS, 1);
    convert_split<<<cvw, 256>>>(Wk, W3, DMODEL, 0);
    gemm_mma<<<gg, 256, GSMEM>>>(A3, W3, (float*)pK, 1);

    convert_split<<<cva, 256>>>(v, A3, MROWS, 1);
    convert_split<<<cvw, 256>>>(Wv, W3, DMODEL, 0);
    gemm_mma<<<gg, 256, GSMEM>>>(A3, W3, (float*)pV, 1);

    split_bf16<<<cvs, 256>>>((const float*)pQ, (__nv_bfloat16*)pQh, (__nv_bfloat16*)pQl);
    split_bf16<<<cvs, 256>>>((const float*)pK, (__nv_bfloat16*)pKh, (__nv_bfloat16*)pKl);
    split_bf16<<<cvs, 256>>>((const float*)pV, (__nv_bfloat16*)pVh, (__nv_bfloat16*)pVl);

    cudaFuncSetAttribute(flash_mma, cudaFuncAttributeMaxDynamicSharedMemorySize, FSMEM);
    flash_mma<<<dim3(TSEQ / 128, BHEADS), 256, FSMEM>>>();

    convert_split<<<cva, 256>>>((const float*)pC, A3, MROWS, 1);
    convert_split<<<cvw, 256>>>(Wo, W3, DMODEL, 0);
    gemm_mma<<<gg, 256, GSMEM>>>(A3, W3, out, 0);

    const long long n_out = (long long)MROWS * DMODEL;
    const long long n_aw  = (long long)BHEADS * TSEQ * TSEQ;
    if ((long long)out_size >= n_out + n_aw) {
        attn_weights<<<dim3(TSEQ / 64, TSEQ / 64, BHEADS), 256>>>(out + (size_t)n_out);
    }
}